// round 11
// baseline (speedup 1.0000x reference)
#include <cuda_runtime.h>
#include <cuda_bf16.h>
#include <math.h>
#include <stdint.h>

// Problem constants
#define B_  2
#define T_  2048
#define C_  1024
#define H_  16
#define D_  64
#define M_  (B_*T_)        // 4096 rows
#define TC  64             // chunk length for linear attention
#define NC  (T_/TC)        // 32 chunks

// ---------------- scratch (device globals; no cudaMalloc allowed) ----------
__device__ __nv_bfloat16 g_xnh[(size_t)M_*C_];      // normalized x, bf16 hi
__device__ __nv_bfloat16 g_xnl[(size_t)M_*C_];      // normalized x, bf16 lo
__device__ __nv_bfloat16 g_w1h[(size_t)3*C_*C_];
__device__ __nv_bfloat16 g_w1l[(size_t)3*C_*C_];
__device__ __nv_bfloat16 g_w2h[(size_t)C_*C_];
__device__ __nv_bfloat16 g_w2l[(size_t)C_*C_];
__device__ __nv_bfloat16 g_yh[(size_t)M_*C_];       // attention out hi
__device__ __nv_bfloat16 g_yl[(size_t)M_*C_];       // attention out lo
__device__ float g_qkv[(size_t)M_*3*C_];            // qkv fp32 (elu applied q,k)
__device__ float g_kv[(size_t)B_*H_*NC*D_*D_];      // per-chunk K^T V -> excl prefix
__device__ float g_ksum[B_*H_*NC*D_];               // per-chunk k sums -> excl prefix

// ---------------- PTX helpers -----------------------------------------------
__device__ __forceinline__ uint32_t smem_u32(const void* p) {
    uint32_t a;
    asm("{ .reg .u64 t; cvta.to.shared.u64 t, %1; cvt.u32.u64 %0, t; }"
        : "=r"(a) : "l"(p));
    return a;
}
#define CPA16(sm, gm) \
    asm volatile("cp.async.cg.shared.global [%0], [%1], 16;" :: "r"(sm), "l"(gm))
#define CPA_COMMIT() asm volatile("cp.async.commit_group;" ::: "memory")
#define CPA_WAIT1()  asm volatile("cp.async.wait_group 1;" ::: "memory")
#define CPA_WAIT0()  asm volatile("cp.async.wait_group 0;" ::: "memory")

__device__ __forceinline__ void ldsm_x4(uint32_t* r, uint32_t addr) {
    asm volatile("ldmatrix.sync.aligned.m8n8.x4.shared.b16 {%0,%1,%2,%3}, [%4];"
                 : "=r"(r[0]), "=r"(r[1]), "=r"(r[2]), "=r"(r[3]) : "r"(addr));
}
__device__ __forceinline__ void mma_bf16(float* c, const uint32_t* a, const uint32_t* b) {
    asm volatile("mma.sync.aligned.m16n8k16.row.col.f32.bf16.bf16.f32 "
        "{%0,%1,%2,%3}, {%4,%5,%6,%7}, {%8,%9}, {%0,%1,%2,%3};"
        : "+f"(c[0]), "+f"(c[1]), "+f"(c[2]), "+f"(c[3])
        : "r"(a[0]), "r"(a[1]), "r"(a[2]), "r"(a[3]), "r"(b[0]), "r"(b[1]));
}

__device__ __forceinline__ uint32_t pack_hi2(float a, float b) {
    __nv_bfloat162 t;
    t.x = __float2bfloat16(a); t.y = __float2bfloat16(b);
    return *(uint32_t*)&t;
}
__device__ __forceinline__ void split4(const float* v, uint32_t* hi, uint32_t* lo) {
    __nv_bfloat16 h[4]; float r[4];
    #pragma unroll
    for (int i = 0; i < 4; i++) { h[i] = __float2bfloat16(v[i]); r[i] = v[i] - __bfloat162float(h[i]); }
    __nv_bfloat162 p0, p1; p0.x = h[0]; p0.y = h[1]; p1.x = h[2]; p1.y = h[3];
    hi[0] = *(uint32_t*)&p0; hi[1] = *(uint32_t*)&p1;
    lo[0] = pack_hi2(r[0], r[1]); lo[1] = pack_hi2(r[2], r[3]);
}

// ---------------- 1. LayerNorm -> bf16 hi/lo --------------------------------
__global__ __launch_bounds__(256) void ln_kernel(const float* __restrict__ x) {
    int row = blockIdx.x;
    const float4* xr = (const float4*)(x + (size_t)row * C_);
    float4 v = xr[threadIdx.x];
    float s  = v.x + v.y + v.z + v.w;
    float sq = v.x*v.x + v.y*v.y + v.z*v.z + v.w*v.w;
    __shared__ float ss[8], ssq[8];
    #pragma unroll
    for (int o = 16; o; o >>= 1) {
        s  += __shfl_xor_sync(0xffffffffu, s,  o);
        sq += __shfl_xor_sync(0xffffffffu, sq, o);
    }
    if ((threadIdx.x & 31) == 0) { ss[threadIdx.x >> 5] = s; ssq[threadIdx.x >> 5] = sq; }
    __syncthreads();
    s = 0.f; sq = 0.f;
    #pragma unroll
    for (int i = 0; i < 8; i++) { s += ss[i]; sq += ssq[i]; }
    float mean = s * (1.0f / C_);
    float var  = sq * (1.0f / C_) - mean * mean;
    float rstd = rsqrtf(var + 1e-5f);
    float o[4] = { (v.x - mean) * rstd, (v.y - mean) * rstd,
                   (v.z - mean) * rstd, (v.w - mean) * rstd };
    uint32_t hi[2], lo[2];
    split4(o, hi, lo);
    size_t off = (size_t)row * C_ + threadIdx.x * 4;
    *(uint2*)(g_xnh + off) = make_uint2(hi[0], hi[1]);
    *(uint2*)(g_xnl + off) = make_uint2(lo[0], lo[1]);
}

// ---------------- weight split fp32 -> bf16 hi/lo ---------------------------
__global__ __launch_bounds__(256) void convert_w(
    const float* __restrict__ W, __nv_bfloat16* __restrict__ Wh,
    __nv_bfloat16* __restrict__ Wl, int n4)
{
    int i = blockIdx.x * 256 + threadIdx.x;
    if (i >= n4) return;
    float4 v = ((const float4*)W)[i];
    float a[4] = { v.x, v.y, v.z, v.w };
    uint32_t hi[2], lo[2];
    split4(a, hi, lo);
    ((uint2*)Wh)[i] = make_uint2(hi[0], hi[1]);
    ((uint2*)Wl)[i] = make_uint2(lo[0], lo[1]);
}

// ---------------- mma.sync split-bf16 GEMM  C = A * B^T ---------------------
// 128x128 CTA tile, 8 warps (warp tile 32x64), BK=32.
// 3-stage cp.async ring, ONE __syncthreads per k-chunk, XOR-swizzled smem.
// 3 split terms: AhBh + AlBh + AhBl, fp32 accum.
// Distance-8 schedule with only 8 live B regs: per np-pair load bH0+bH1,
// HH x8 (8 distinct accs) then LH x8 (distance 8), bH dead, load bL0+bL1,
// HL x8. (R9 failed because 16 live B regs -> 132 regs -> 1 CTA/SM.)
// __launch_bounds__(256, 2) pins 2 CTAs/SM (<=128 regs).
#define OFF_AH 0
#define OFF_AL 8192
#define OFF_BH 16384
#define OFF_BL 24576
#define BUF_BYTES 32768
#define GEMM_DSMEM (3*BUF_BYTES)

__device__ __forceinline__ void gstage(
    char* smbuf,
    const __nv_bfloat16* __restrict__ Ah, const __nv_bfloat16* __restrict__ Al,
    const __nv_bfloat16* __restrict__ Bh, const __nv_bfloat16* __restrict__ Bl,
    int m0, int n0, int K, int k0, int tid)
{
    int row = tid >> 1;
    int c0  = tid & 1;
    uint32_t sr = smem_u32(smbuf) + row * 64;
    uint32_t sz = (row >> 1) & 3;
    const __nv_bfloat16* pah = Ah + (size_t)(m0 + row) * K + k0;
    const __nv_bfloat16* pal = Al + (size_t)(m0 + row) * K + k0;
    const __nv_bfloat16* pbh = Bh + (size_t)(n0 + row) * K + k0;
    const __nv_bfloat16* pbl = Bl + (size_t)(n0 + row) * K + k0;
    #pragma unroll
    for (int cc = 0; cc < 2; cc++) {
        int c = c0 + cc * 2;                 // 16B chunk 0..3
        uint32_t sw = (uint32_t)(c ^ sz) << 4;
        CPA16(sr + OFF_AH + sw, pah + c * 8);
        CPA16(sr + OFF_AL + sw, pal + c * 8);
        CPA16(sr + OFF_BH + sw, pbh + c * 8);
        CPA16(sr + OFF_BL + sw, pbl + c * 8);
    }
}

template<bool ELU>
__global__ __launch_bounds__(256, 2) void mmagemm(
    const __nv_bfloat16* __restrict__ Ah, const __nv_bfloat16* __restrict__ Al,
    const __nv_bfloat16* __restrict__ Bh, const __nv_bfloat16* __restrict__ Bl,
    float* __restrict__ Cm, int M, int N, int K, int elu_ncut)
{
    extern __shared__ __align__(128) char smx[];
    int tid = threadIdx.x, lane = tid & 31, wid = tid >> 5;
    int m0 = blockIdx.y * 128, n0 = blockIdx.x * 128;
    int wm = (wid & 3) * 32;            // warp m offset (2 m16 tiles)
    int wn = (wid >> 2) * 64;           // warp n offset (4 n16 tiles)

    float acc[2][8][4];
    #pragma unroll
    for (int mt = 0; mt < 2; mt++)
        #pragma unroll
        for (int nt = 0; nt < 8; nt++)
            #pragma unroll
            for (int k = 0; k < 4; k++) acc[mt][nt][k] = 0.f;

    int nk = K >> 5;                    // K/32 chunks
    gstage(smx,             Ah, Al, Bh, Bl, m0, n0, K, 0,  tid); CPA_COMMIT();
    gstage(smx + BUF_BYTES, Ah, Al, Bh, Bl, m0, n0, K, 32, tid); CPA_COMMIT();

    // ldmatrix lane addressing
    int a_row = lane & 15, a_c = lane >> 4;
    int b_row = (lane & 7) + (lane >> 4) * 8, b_c = (lane >> 3) & 1;
    uint32_t a_sw = (uint32_t)((a_row >> 1) & 3);
    uint32_t b_sw = (uint32_t)((b_row >> 1) & 3);

    int s_cur = 0, s_stage = 2;
    for (int kc = 0; kc < nk; kc++) {
        if (kc + 1 < nk) { CPA_WAIT1(); } else { CPA_WAIT0(); }
        __syncthreads();
        if (kc + 2 < nk) {
            gstage(smx + s_stage * BUF_BYTES, Ah, Al, Bh, Bl,
                   m0, n0, K, (kc + 2) * 32, tid);
            CPA_COMMIT();
            if (++s_stage == 3) s_stage = 0;
        }
        uint32_t sb = smem_u32(smx) + s_cur * BUF_BYTES;
        if (++s_cur == 3) s_cur = 0;

        #pragma unroll
        for (int ks = 0; ks < 2; ks++) {
            uint32_t aH[2][4], aL[2][4];
            uint32_t ac = (uint32_t)((ks * 2 + a_c) ^ a_sw) << 4;
            #pragma unroll
            for (int mt = 0; mt < 2; mt++) {
                uint32_t ar = sb + (wm + mt * 16 + a_row) * 64 + ac;
                ldsm_x4(aH[mt], ar + OFF_AH);
                ldsm_x4(aL[mt], ar + OFF_AL);
            }
            uint32_t bc = (uint32_t)((ks * 2 + b_c) ^ b_sw) << 4;
            #pragma unroll
            for (int npp = 0; npp < 2; npp++) {
                uint32_t br0 = sb + (wn + (npp*2+0) * 16 + b_row) * 64 + bc;
                uint32_t br1 = sb + (wn + (npp*2+1) * 16 + b_row) * 64 + bc;
                float* a00 = acc[0][npp*4+0]; float* a01 = acc[0][npp*4+1];
                float* a02 = acc[0][npp*4+2]; float* a03 = acc[0][npp*4+3];
                float* a10 = acc[1][npp*4+0]; float* a11 = acc[1][npp*4+1];
                float* a12 = acc[1][npp*4+2]; float* a13 = acc[1][npp*4+3];
                {
                    uint32_t bH0[4], bH1[4];
                    ldsm_x4(bH0, br0 + OFF_BH);
                    ldsm_x4(bH1, br1 + OFF_BH);
                    // HH: 8 distinct accumulators
                    mma_bf16(a00, aH[0], bH0);
                    mma_bf16(a01, aH[0], bH0 + 2);
                    mma_bf16(a10, aH[1], bH0);
                    mma_bf16(a11, aH[1], bH0 + 2);
                    mma_bf16(a02, aH[0], bH1);
                    mma_bf16(a03, aH[0], bH1 + 2);
                    mma_bf16(a12, aH[1], bH1);
                    mma_bf16(a13, aH[1], bH1 + 2);
                    // LH: same 8 accs, reuse distance 8
                    mma_bf16(a00, aL[0], bH0);
                    mma_bf16(a01, aL[0], bH0 + 2);
                    mma_bf16(a10, aL[1], bH0);
                    mma_bf16(a11, aL[1], bH0 + 2);
                    mma_bf16(a02, aL[0], bH1);
                    mma_bf16(a03, aL[0], bH1 + 2);
                    mma_bf16(a12, aL[1], bH1);
                    mma_bf16(a13, aL[1], bH1 + 2);
                }
                {
                    uint32_t bL0[4], bL1[4];
                    ldsm_x4(bL0, br0 + OFF_BL);
                    ldsm_x4(bL1, br1 + OFF_BL);
                    // HL: 8 distinct accumulators again
                    mma_bf16(a00, aH[0], bL0);
                    mma_bf16(a01, aH[0], bL0 + 2);
                    mma_bf16(a10, aH[1], bL0);
                    mma_bf16(a11, aH[1], bL0 + 2);
                    mma_bf16(a02, aH[0], bL1);
                    mma_bf16(a03, aH[0], bL1 + 2);
                    mma_bf16(a12, aH[1], bL1);
                    mma_bf16(a13, aH[1], bL1 + 2);
                }
            }
        }
    }

    // epilogue
    bool doelu = ELU && (n0 < elu_ncut);
    int r = lane >> 2, cp2 = (lane & 3) * 2;
    #pragma unroll
    for (int mt = 0; mt < 2; mt++) {
        #pragma unroll
        for (int nt = 0; nt < 8; nt++) {
            int mrow = m0 + wm + mt * 16 + r;
            int ncol = n0 + wn + nt * 8 + cp2;
            float v0 = acc[mt][nt][0], v1 = acc[mt][nt][1];
            float v2 = acc[mt][nt][2], v3 = acc[mt][nt][3];
            if (doelu) {
                v0 = v0 > 0.f ? v0 + 1.f : expf(v0);
                v1 = v1 > 0.f ? v1 + 1.f : expf(v1);
                v2 = v2 > 0.f ? v2 + 1.f : expf(v2);
                v3 = v3 > 0.f ? v3 + 1.f : expf(v3);
            }
            *(float2*)(Cm + (size_t)mrow * N + ncol)       = make_float2(v0, v1);
            *(float2*)(Cm + (size_t)(mrow + 8) * N + ncol) = make_float2(v2, v3);
        }
    }
}

// ---------------- 3a. per-chunk K^T V and k-sums ----------------------------
__global__ __launch_bounds__(256) void chunk_kv_kernel() {
    int c = blockIdx.x, h = blockIdx.y, b = blockIdx.z;
    __shared__ float sK[TC * D_], sV[TC * D_];
    int tid = threadIdx.x;
    const float* base = g_qkv + ((size_t)(b * T_ + c * TC)) * (3 * C_) + h * D_;
    for (int i = tid; i < TC * D_ / 4; i += 256) {
        int t = i >> 4, d4 = (i & 15) * 4;
        *(float4*)&sK[t * D_ + d4] = *(const float4*)(base + (size_t)t * 3 * C_ + C_     + d4);
        *(float4*)&sV[t * D_ + d4] = *(const float4*)(base + (size_t)t * 3 * C_ + 2 * C_ + d4);
    }
    __syncthreads();
    int tx = tid & 15, ty = tid >> 4;
    float acc[4][4];
    #pragma unroll
    for (int i = 0; i < 4; i++)
        #pragma unroll
        for (int j = 0; j < 4; j++) acc[i][j] = 0.f;
    for (int t = 0; t < TC; t++) {
        float kv[4];
        #pragma unroll
        for (int i = 0; i < 4; i++) kv[i] = sK[t * D_ + ty * 4 + i];
        float4 vv = *(const float4*)&sV[t * D_ + tx * 4];
        #pragma unroll
        for (int i = 0; i < 4; i++) {
            acc[i][0] += kv[i] * vv.x;
            acc[i][1] += kv[i] * vv.y;
            acc[i][2] += kv[i] * vv.z;
            acc[i][3] += kv[i] * vv.w;
        }
    }
    float* out = g_kv + ((size_t)((b * H_ + h) * NC + c)) * (D_ * D_);
    #pragma unroll
    for (int i = 0; i < 4; i++)
        *(float4*)(out + (ty * 4 + i) * D_ + tx * 4) =
            make_float4(acc[i][0], acc[i][1], acc[i][2], acc[i][3]);
    if (tid < D_) {
        float s = 0.f;
        for (int t = 0; t < TC; t++) s += sK[t * D_ + tid];
        g_ksum[((b * H_ + h) * NC + c) * D_ + tid] = s;
    }
}

// ---------------- 3b. exclusive prefix over chunks (parallel) ---------------
__global__ __launch_bounds__(256) void prefix_kernel() {
    int h = blockIdx.y, b = blockIdx.z;
    int e = blockIdx.x * 256 + threadIdx.x;
    size_t base = (size_t)(b * H_ + h) * NC * (D_ * D_) + e;
    float v[NC];
    #pragma unroll
    for (int c = 0; c < NC; c++) v[c] = g_kv[base + (size_t)c * (D_ * D_)];
    float acc = 0.f;
    #pragma unroll
    for (int c = 0; c < NC; c++) { float t = v[c]; v[c] = acc; acc += t; }
    #pragma unroll
    for (int c = 0; c < NC; c++) g_kv[base + (size_t)c * (D_ * D_)] = v[c];

    if (blockIdx.x == 0 && threadIdx.x < D_) {
        size_t kb = (size_t)(b * H_ + h) * NC * D_ + threadIdx.x;
        float w[NC];
        #pragma unroll
        for (int c = 0; c < NC; c++) w[c] = g_ksum[kb + c * D_];
        float a = 0.f;
        #pragma unroll
        for (int c = 0; c < NC; c++) { float t = w[c]; w[c] = a; a += t; }
        #pragma unroll
        for (int c = 0; c < NC; c++) g_ksum[kb + c * D_] = w[c];
    }
}

// ---------------- 3c. per-chunk output -> y bf16 hi/lo ----------------------
__global__ __launch_bounds__(256) void attn_out_kernel() {
    int c = blockIdx.x, h = blockIdx.y, b = blockIdx.z;
    __shared__ float sQ[TC * D_];
    __shared__ float sB_[TC * D_];
    __shared__ float sA[TC * TC];
    int tid = threadIdx.x, tx = tid & 15, ty = tid >> 4;
    const float* qbase = g_qkv + ((size_t)(b * T_ + c * TC)) * (3 * C_) + h * D_;

    for (int i = tid; i < TC * D_ / 4; i += 256) {
        int t = i >> 4, d4 = (i & 15) * 4;
        *(float4*)&sQ[t * D_ + d4]  = *(const float4*)(qbase + (size_t)t * 3 * C_ + d4);
        *(float4*)&sB_[t * D_ + d4] = *(const float4*)(qbase + (size_t)t * 3 * C_ + C_ + d4);
    }
    __syncthreads();

    {
        float acc[4][4];
        #pragma unroll
        for (int i = 0; i < 4; i++)
            #pragma unroll
            for (int j = 0; j < 4; j++) acc[i][j] = 0.f;
        for (int k = 0; k < D_; k += 4) {
            float4 a4[4], b4[4];
            #pragma unroll
            for (int i = 0; i < 4; i++) a4[i] = *(const float4*)&sQ[(ty * 4 + i) * D_ + k];
            #pragma unroll
            for (int j = 0; j < 4; j++) b4[j] = *(const float4*)&sB_[(tx * 4 + j) * D_ + k];
            #pragma unroll
            for (int i = 0; i < 4; i++)
                #pragma unroll
                for (int j = 0; j < 4; j++)
                    acc[i][j] += a4[i].x * b4[j].x + a4[i].y * b4[j].y
                               + a4[i].z * b4[j].z + a4[i].w * b4[j].w;
        }
        #pragma unroll
        for (int i = 0; i < 4; i++)
            #pragma unroll
            for (int j = 0; j < 4; j++) {
                int t = ty * 4 + i, s = tx * 4 + j;
                sA[t * TC + s] = (s <= t) ? acc[i][j] : 0.f;
            }
    }
    __syncthreads();

    float denreg = 0.f;
    if (tid < TC) {
        int t = tid;
        for (int s = 0; s < TC; s++) denreg += sA[t * TC + s];
        const float* z = g_ksum + ((size_t)(b * H_ + h) * NC + c) * D_;
        for (int k = 0; k < D_; k++) denreg += sQ[t * D_ + k] * __ldg(z + k);
    }
    for (int i = tid; i < TC * D_ / 4; i += 256) {
        int t = i >> 4, d4 = (i & 15) * 4;
        *(float4*)&sB_[t * D_ + d4] = *(const float4*)(qbase + (size_t)t * 3 * C_ + 2 * C_ + d4);
    }
    __syncthreads();

    float out[4][4];
    #pragma unroll
    for (int i = 0; i < 4; i++)
        #pragma unroll
        for (int j = 0; j < 4; j++) out[i][j] = 0.f;
    for (int s = 0; s < TC; s++) {
        float a[4];
        #pragma unroll
        for (int i = 0; i < 4; i++) a[i] = sA[(ty * 4 + i) * TC + s];
        float4 vv = *(const float4*)&sB_[s * D_ + tx * 4];
        #pragma unroll
        for (int i = 0; i < 4; i++) {
            out[i][0] += a[i] * vv.x;
            out[i][1] += a[i] * vv.y;
            out[i][2] += a[i] * vv.z;
            out[i][3] += a[i] * vv.w;
        }
    }
    __syncthreads();

    if (tid < TC) sA[tid] = denreg;
    const float* Sg = g_kv + ((size_t)((b * H_ + h) * NC + c)) * (D_ * D_);
    for (int i = tid; i < TC * D_ / 4; i += 256)
        *(float4*)&sB_[i * 4] = *(const float4*)(Sg + i * 4);
    __syncthreads();

    for (int k = 0; k < D_; k++) {
        float a[4];
        #pragma unroll
        for (int i = 0; i < 4; i++) a[i] = sQ[(ty * 4 + i) * D_ + k];
        float4 sv = *(const float4*)&sB_[k * D_ + tx * 4];
        #pragma unroll
        for (int i = 0; i < 4; i++) {
            out[i][0] += a[i] * sv.x;
            out[i][1] += a[i] * sv.y;
            out[i][2] += a[i] * sv.z;
            out[i][3] += a[i] * sv.w;
        }
    }

    // normalize + store bf16 hi/lo to y in [B,T,C] layout
    size_t ybase = ((size_t)(b * T_ + c * TC)) * C_ + h * D_;
    #pragma unroll
    for (int i = 0; i < 4; i++) {
        int t = ty * 4 + i;
        float invd = 1.0f / sA[t];
        float v[4] = { out[i][0] * invd, out[i][1] * invd,
                       out[i][2] * invd, out[i][3] * invd };
        uint32_t hi[2], lo[2];
        split4(v, hi, lo);
        size_t off = ybase + (size_t)t * C_ + tx * 4;
        *(uint2*)(g_yh + off) = make_uint2(hi[0], hi[1]);
        *(uint2*)(g_yl + off) = make_uint2(lo[0], lo[1]);
    }
}

// ---------------- launch ----------------------------------------------------
extern "C" void kernel_launch(void* const* d_in, const int* in_sizes, int n_in,
                              void* d_out, int out_size) {
    const float* x  = (const float*)d_in[0];   // [B,T,C]
    const float* W1 = (const float*)d_in[1];   // [3C,C]
    const float* W2 = (const float*)d_in[2];   // [C,C]
    float* out = (float*)d_out;                // [B,T,C]

    __nv_bfloat16 *xnh, *xnl, *w1h, *w1l, *w2h, *w2l, *yh, *yl;
    float* qkv;
    cudaGetSymbolAddress((void**)&xnh, g_xnh);
    cudaGetSymbolAddress((void**)&xnl, g_xnl);
    cudaGetSymbolAddress((void**)&w1h, g_w1h);
    cudaGetSymbolAddress((void**)&w1l, g_w1l);
    cudaGetSymbolAddress((void**)&w2h, g_w2h);
    cudaGetSymbolAddress((void**)&w2l, g_w2l);
    cudaGetSymbolAddress((void**)&yh,  g_yh);
    cudaGetSymbolAddress((void**)&yl,  g_yl);
    cudaGetSymbolAddress((void**)&qkv, g_qkv);

    cudaFuncSetAttribute(mmagemm<true>,  cudaFuncAttributeMaxDynamicSharedMemorySize, GEMM_DSMEM);
    cudaFuncSetAttribute(mmagemm<false>, cudaFuncAttributeMaxDynamicSharedMemorySize, GEMM_DSMEM);

    // 1. layernorm -> bf16 hi/lo
    ln_kernel<<<M_, 256>>>(x);

    // weight splits
    convert_w<<<(3 * C_ * C_ / 4 + 255) / 256, 256>>>(W1, w1h, w1l, 3 * C_ * C_ / 4);
    convert_w<<<(C_ * C_ / 4 + 255) / 256, 256>>>(W2, w2h, w2l, C_ * C_ / 4);

    // 2. qkv = xn @ W1^T (mma.sync split-bf16), elu+1 on q,k columns
    {
        dim3 grid(3 * C_ / 128, M_ / 128);
        mmagemm<true><<<grid, 256, GEMM_DSMEM>>>(xnh, xnl, w1h, w1l, qkv,
                                                 M_, 3 * C_, C_, 2 * C_);
    }

    // 3. linear attention (chunked, exact)
    {
        dim3 gA(NC, H_, B_);
        chunk_kv_kernel<<<gA, 256>>>();
        dim3 gP(D_ * D_ / 256, H_, B_);
        prefix_kernel<<<gP, 256>>>();
        attn_out_kernel<<<gA, 256>>>();
    }

    // 4. out = y @ W2^T (mma.sync split-bf16)
    {
        dim3 grid(C_ / 128, M_ / 128);
        mmagemm<false><<<grid, 256, GEMM_DSMEM>>>(yh, yl, w2h, w2l, out,
                                                  M_, C_, C_, 0);
    }
}

// round 12
// speedup vs baseline: 1.2628x; 1.2628x over previous
#include <cuda_runtime.h>
#include <cuda_fp16.h>
#include <math.h>
#include <stdint.h>

// Problem constants
#define B_  2
#define T_  2048
#define C_  1024
#define H_  16
#define D_  64
#define M_  (B_*T_)        // 4096 rows
#define TC  64             // chunk length for linear attention
#define NC  (T_/TC)        // 32 chunks

// ---------------- scratch (device globals; no cudaMalloc allowed) ----------
__device__ __half g_xnh[(size_t)M_*C_];      // normalized x, fp16 hi
__device__ __half g_xnl[(size_t)M_*C_];      // normalized x, fp16 residual
__device__ __half g_w1h[(size_t)3*C_*C_];    // W1 fp16 (truncated)
__device__ __half g_w2h[(size_t)C_*C_];      // W2 fp16 (truncated)
__device__ __half g_yh[(size_t)M_*C_];       // attention out fp16 hi
__device__ __half g_yl[(size_t)M_*C_];       // attention out fp16 residual
__device__ float g_qkv[(size_t)M_*3*C_];     // qkv fp32 (elu applied q,k)
__device__ float g_kv[(size_t)B_*H_*NC*D_*D_];
__device__ float g_ksum[B_*H_*NC*D_];

// ---------------- PTX helpers -----------------------------------------------
__device__ __forceinline__ uint32_t smem_u32(const void* p) {
    uint32_t a;
    asm("{ .reg .u64 t; cvta.to.shared.u64 t, %1; cvt.u32.u64 %0, t; }"
        : "=r"(a) : "l"(p));
    return a;
}
#define CPA16(sm, gm) \
    asm volatile("cp.async.cg.shared.global [%0], [%1], 16;" :: "r"(sm), "l"(gm))
#define CPA_COMMIT() asm volatile("cp.async.commit_group;" ::: "memory")
#define CPA_WAIT1()  asm volatile("cp.async.wait_group 1;" ::: "memory")
#define CPA_WAIT0()  asm volatile("cp.async.wait_group 0;" ::: "memory")

__device__ __forceinline__ void ldsm_x4(uint32_t* r, uint32_t addr) {
    asm volatile("ldmatrix.sync.aligned.m8n8.x4.shared.b16 {%0,%1,%2,%3}, [%4];"
                 : "=r"(r[0]), "=r"(r[1]), "=r"(r[2]), "=r"(r[3]) : "r"(addr));
}
__device__ __forceinline__ void mma_f16(float* c, const uint32_t* a, const uint32_t* b) {
    asm volatile("mma.sync.aligned.m16n8k16.row.col.f32.f16.f16.f32 "
        "{%0,%1,%2,%3}, {%4,%5,%6,%7}, {%8,%9}, {%0,%1,%2,%3};"
        : "+f"(c[0]), "+f"(c[1]), "+f"(c[2]), "+f"(c[3])
        : "r"(a[0]), "r"(a[1]), "r"(a[2]), "r"(a[3]), "r"(b[0]), "r"(b[1]));
}

__device__ __forceinline__ uint32_t packh2(__half a, __half b) {
    __half2 t = __halves2half2(a, b);
    return *(uint32_t*)&t;
}
// fp16 hi/residual split of 4 floats
__device__ __forceinline__ void split4h(const float* v, uint32_t* hi, uint32_t* lo) {
    __half h[4]; __half l[4];
    #pragma unroll
    for (int i = 0; i < 4; i++) {
        h[i] = __float2half_rn(v[i]);
        l[i] = __float2half_rn(v[i] - __half2float(h[i]));
    }
    hi[0] = packh2(h[0], h[1]); hi[1] = packh2(h[2], h[3]);
    lo[0] = packh2(l[0], l[1]); lo[1] = packh2(l[2], l[3]);
}

// ---------------- 1. LayerNorm -> fp16 hi/lo --------------------------------
__global__ __launch_bounds__(256) void ln_kernel(const float* __restrict__ x) {
    int row = blockIdx.x;
    const float4* xr = (const float4*)(x + (size_t)row * C_);
    float4 v = xr[threadIdx.x];
    float s  = v.x + v.y + v.z + v.w;
    float sq = v.x*v.x + v.y*v.y + v.z*v.z + v.w*v.w;
    __shared__ float ss[8], ssq[8];
    #pragma unroll
    for (int o = 16; o; o >>= 1) {
        s  += __shfl_xor_sync(0xffffffffu, s,  o);
        sq += __shfl_xor_sync(0xffffffffu, sq, o);
    }
    if ((threadIdx.x & 31) == 0) { ss[threadIdx.x >> 5] = s; ssq[threadIdx.x >> 5] = sq; }
    __syncthreads();
    s = 0.f; sq = 0.f;
    #pragma unroll
    for (int i = 0; i < 8; i++) { s += ss[i]; sq += ssq[i]; }
    float mean = s * (1.0f / C_);
    float var  = sq * (1.0f / C_) - mean * mean;
    float rstd = rsqrtf(var + 1e-5f);
    float o[4] = { (v.x - mean) * rstd, (v.y - mean) * rstd,
                   (v.z - mean) * rstd, (v.w - mean) * rstd };
    uint32_t hi[2], lo[2];
    split4h(o, hi, lo);
    size_t off = (size_t)row * C_ + threadIdx.x * 4;
    *(uint2*)(g_xnh + off) = make_uint2(hi[0], hi[1]);
    *(uint2*)(g_xnl + off) = make_uint2(lo[0], lo[1]);
}

// ---------------- weight convert fp32 -> fp16 (truncate) --------------------
__global__ __launch_bounds__(256) void convert_w(
    const float* __restrict__ W, __half* __restrict__ Wh, int n4)
{
    int i = blockIdx.x * 256 + threadIdx.x;
    if (i >= n4) return;
    float4 v = ((const float4*)W)[i];
    uint2 o;
    o.x = packh2(__float2half_rn(v.x), __float2half_rn(v.y));
    o.y = packh2(__float2half_rn(v.z), __float2half_rn(v.w));
    ((uint2*)Wh)[i] = o;
}

// ---------------- mma.sync 2-term fp16 GEMM  C = (Ah+Al) * Bh^T -------------
// 128x128 CTA tile, 8 warps (warp tile 32x64), BK=32.
// 3-stage cp.async ring, ONE __syncthreads per k-chunk, XOR-swizzled smem.
// 2 terms: AhBh + AlBh, fp32 accum. Weight-truncation error ~eps_fp16 ~ 2e-4.
// __launch_bounds__(256, 2) pins 2 CTAs/SM (<=128 regs).
#define OFF_AH 0
#define OFF_AL 8192
#define OFF_BH 16384
#define BUF_BYTES 24576
#define GEMM_DSMEM (3*BUF_BYTES)

__device__ __forceinline__ void gstage(
    char* smbuf,
    const __half* __restrict__ Ah, const __half* __restrict__ Al,
    const __half* __restrict__ Bh,
    int m0, int n0, int K, int k0, int tid)
{
    int row = tid >> 1;
    int c0  = tid & 1;
    uint32_t sr = smem_u32(smbuf) + row * 64;
    uint32_t sz = (row >> 1) & 3;
    const __half* pah = Ah + (size_t)(m0 + row) * K + k0;
    const __half* pal = Al + (size_t)(m0 + row) * K + k0;
    const __half* pbh = Bh + (size_t)(n0 + row) * K + k0;
    #pragma unroll
    for (int cc = 0; cc < 2; cc++) {
        int c = c0 + cc * 2;                 // 16B chunk 0..3
        uint32_t sw = (uint32_t)(c ^ sz) << 4;
        CPA16(sr + OFF_AH + sw, pah + c * 8);
        CPA16(sr + OFF_AL + sw, pal + c * 8);
        CPA16(sr + OFF_BH + sw, pbh + c * 8);
    }
}

template<bool ELU>
__global__ __launch_bounds__(256, 2) void mmagemm(
    const __half* __restrict__ Ah, const __half* __restrict__ Al,
    const __half* __restrict__ Bh,
    float* __restrict__ Cm, int M, int N, int K, int elu_ncut)
{
    extern __shared__ __align__(128) char smx[];
    int tid = threadIdx.x, lane = tid & 31, wid = tid >> 5;
    int m0 = blockIdx.y * 128, n0 = blockIdx.x * 128;
    int wm = (wid & 3) * 32;            // warp m offset (2 m16 tiles)
    int wn = (wid >> 2) * 64;           // warp n offset (4 n16 tiles)

    float acc[2][8][4];
    #pragma unroll
    for (int mt = 0; mt < 2; mt++)
        #pragma unroll
        for (int nt = 0; nt < 8; nt++)
            #pragma unroll
            for (int k = 0; k < 4; k++) acc[mt][nt][k] = 0.f;

    int nk = K >> 5;                    // K/32 chunks
    gstage(smx,             Ah, Al, Bh, m0, n0, K, 0,  tid); CPA_COMMIT();
    gstage(smx + BUF_BYTES, Ah, Al, Bh, m0, n0, K, 32, tid); CPA_COMMIT();

    // ldmatrix lane addressing
    int a_row = lane & 15, a_c = lane >> 4;
    int b_row = (lane & 7) + (lane >> 4) * 8, b_c = (lane >> 3) & 1;
    uint32_t a_sw = (uint32_t)((a_row >> 1) & 3);
    uint32_t b_sw = (uint32_t)((b_row >> 1) & 3);

    int s_cur = 0, s_stage = 2;
    for (int kc = 0; kc < nk; kc++) {
        if (kc + 1 < nk) { CPA_WAIT1(); } else { CPA_WAIT0(); }
        __syncthreads();
        if (kc + 2 < nk) {
            gstage(smx + s_stage * BUF_BYTES, Ah, Al, Bh,
                   m0, n0, K, (kc + 2) * 32, tid);
            CPA_COMMIT();
            if (++s_stage == 3) s_stage = 0;
        }
        uint32_t sb = smem_u32(smx) + s_cur * BUF_BYTES;
        if (++s_cur == 3) s_cur = 0;

        #pragma unroll
        for (int ks = 0; ks < 2; ks++) {
            uint32_t aH[2][4], aL[2][4];
            uint32_t ac = (uint32_t)((ks * 2 + a_c) ^ a_sw) << 4;
            #pragma unroll
            for (int mt = 0; mt < 2; mt++) {
                uint32_t ar = sb + (wm + mt * 16 + a_row) * 64 + ac;
                ldsm_x4(aH[mt], ar + OFF_AH);
                ldsm_x4(aL[mt], ar + OFF_AL);
            }
            uint32_t bc = (uint32_t)((ks * 2 + b_c) ^ b_sw) << 4;
            #pragma unroll
            for (int npp = 0; npp < 2; npp++) {
                uint32_t br0 = sb + (wn + (npp*2+0) * 16 + b_row) * 64 + bc;
                uint32_t br1 = sb + (wn + (npp*2+1) * 16 + b_row) * 64 + bc;
                uint32_t bH0[4], bH1[4];
                ldsm_x4(bH0, br0 + OFF_BH);
                ldsm_x4(bH1, br1 + OFF_BH);
                float* a00 = acc[0][npp*4+0]; float* a01 = acc[0][npp*4+1];
                float* a02 = acc[0][npp*4+2]; float* a03 = acc[0][npp*4+3];
                float* a10 = acc[1][npp*4+0]; float* a11 = acc[1][npp*4+1];
                float* a12 = acc[1][npp*4+2]; float* a13 = acc[1][npp*4+3];
                // HH: 8 distinct accumulators
                mma_f16(a00, aH[0], bH0);
                mma_f16(a01, aH[0], bH0 + 2);
                mma_f16(a10, aH[1], bH0);
                mma_f16(a11, aH[1], bH0 + 2);
                mma_f16(a02, aH[0], bH1);
                mma_f16(a03, aH[0], bH1 + 2);
                mma_f16(a12, aH[1], bH1);
                mma_f16(a13, aH[1], bH1 + 2);
                // LH: same 8 accs (reuse distance 8)
                mma_f16(a00, aL[0], bH0);
                mma_f16(a01, aL[0], bH0 + 2);
                mma_f16(a10, aL[1], bH0);
                mma_f16(a11, aL[1], bH0 + 2);
                mma_f16(a02, aL[0], bH1);
                mma_f16(a03, aL[0], bH1 + 2);
                mma_f16(a12, aL[1], bH1);
                mma_f16(a13, aL[1], bH1 + 2);
            }
        }
    }

    // epilogue
    bool doelu = ELU && (n0 < elu_ncut);
    int r = lane >> 2, cp2 = (lane & 3) * 2;
    #pragma unroll
    for (int mt = 0; mt < 2; mt++) {
        #pragma unroll
        for (int nt = 0; nt < 8; nt++) {
            int mrow = m0 + wm + mt * 16 + r;
            int ncol = n0 + wn + nt * 8 + cp2;
            float v0 = acc[mt][nt][0], v1 = acc[mt][nt][1];
            float v2 = acc[mt][nt][2], v3 = acc[mt][nt][3];
            if (doelu) {
                v0 = v0 > 0.f ? v0 + 1.f : expf(v0);
                v1 = v1 > 0.f ? v1 + 1.f : expf(v1);
                v2 = v2 > 0.f ? v2 + 1.f : expf(v2);
                v3 = v3 > 0.f ? v3 + 1.f : expf(v3);
            }
            *(float2*)(Cm + (size_t)mrow * N + ncol)       = make_float2(v0, v1);
            *(float2*)(Cm + (size_t)(mrow + 8) * N + ncol) = make_float2(v2, v3);
        }
    }
}

// ---------------- 3a. per-chunk K^T V and k-sums ----------------------------
__global__ __launch_bounds__(256) void chunk_kv_kernel() {
    int c = blockIdx.x, h = blockIdx.y, b = blockIdx.z;
    __shared__ float sK[TC * D_], sV[TC * D_];
    int tid = threadIdx.x;
    const float* base = g_qkv + ((size_t)(b * T_ + c * TC)) * (3 * C_) + h * D_;
    for (int i = tid; i < TC * D_ / 4; i += 256) {
        int t = i >> 4, d4 = (i & 15) * 4;
        *(float4*)&sK[t * D_ + d4] = *(const float4*)(base + (size_t)t * 3 * C_ + C_     + d4);
        *(float4*)&sV[t * D_ + d4] = *(const float4*)(base + (size_t)t * 3 * C_ + 2 * C_ + d4);
    }
    __syncthreads();
    int tx = tid & 15, ty = tid >> 4;
    float acc[4][4];
    #pragma unroll
    for (int i = 0; i < 4; i++)
        #pragma unroll
        for (int j = 0; j < 4; j++) acc[i][j] = 0.f;
    for (int t = 0; t < TC; t++) {
        float kv[4];
        #pragma unroll
        for (int i = 0; i < 4; i++) kv[i] = sK[t * D_ + ty * 4 + i];
        float4 vv = *(const float4*)&sV[t * D_ + tx * 4];
        #pragma unroll
        for (int i = 0; i < 4; i++) {
            acc[i][0] += kv[i] * vv.x;
            acc[i][1] += kv[i] * vv.y;
            acc[i][2] += kv[i] * vv.z;
            acc[i][3] += kv[i] * vv.w;
        }
    }
    float* out = g_kv + ((size_t)((b * H_ + h) * NC + c)) * (D_ * D_);
    #pragma unroll
    for (int i = 0; i < 4; i++)
        *(float4*)(out + (ty * 4 + i) * D_ + tx * 4) =
            make_float4(acc[i][0], acc[i][1], acc[i][2], acc[i][3]);
    if (tid < D_) {
        float s = 0.f;
        for (int t = 0; t < TC; t++) s += sK[t * D_ + tid];
        g_ksum[((b * H_ + h) * NC + c) * D_ + tid] = s;
    }
}

// ---------------- 3b. exclusive prefix over chunks (parallel) ---------------
__global__ __launch_bounds__(256) void prefix_kernel() {
    int h = blockIdx.y, b = blockIdx.z;
    int e = blockIdx.x * 256 + threadIdx.x;
    size_t base = (size_t)(b * H_ + h) * NC * (D_ * D_) + e;
    float v[NC];
    #pragma unroll
    for (int c = 0; c < NC; c++) v[c] = g_kv[base + (size_t)c * (D_ * D_)];
    float acc = 0.f;
    #pragma unroll
    for (int c = 0; c < NC; c++) { float t = v[c]; v[c] = acc; acc += t; }
    #pragma unroll
    for (int c = 0; c < NC; c++) g_kv[base + (size_t)c * (D_ * D_)] = v[c];

    if (blockIdx.x == 0 && threadIdx.x < D_) {
        size_t kb = (size_t)(b * H_ + h) * NC * D_ + threadIdx.x;
        float w[NC];
        #pragma unroll
        for (int c = 0; c < NC; c++) w[c] = g_ksum[kb + c * D_];
        float a = 0.f;
        #pragma unroll
        for (int c = 0; c < NC; c++) { float t = w[c]; w[c] = a; a += t; }
        #pragma unroll
        for (int c = 0; c < NC; c++) g_ksum[kb + c * D_] = w[c];
    }
}

// ---------------- 3c. per-chunk output -> y fp16 hi/lo ----------------------
__global__ __launch_bounds__(256) void attn_out_kernel() {
    int c = blockIdx.x, h = blockIdx.y, b = blockIdx.z;
    __shared__ float sQ[TC * D_];
    __shared__ float sB_[TC * D_];
    __shared__ float sA[TC * TC];
    int tid = threadIdx.x, tx = tid & 15, ty = tid >> 4;
    const float* qbase = g_qkv + ((size_t)(b * T_ + c * TC)) * (3 * C_) + h * D_;

    for (int i = tid; i < TC * D_ / 4; i += 256) {
        int t = i >> 4, d4 = (i & 15) * 4;
        *(float4*)&sQ[t * D_ + d4]  = *(const float4*)(qbase + (size_t)t * 3 * C_ + d4);
        *(float4*)&sB_[t * D_ + d4] = *(const float4*)(qbase + (size_t)t * 3 * C_ + C_ + d4);
    }
    __syncthreads();

    {
        float acc[4][4];
        #pragma unroll
        for (int i = 0; i < 4; i++)
            #pragma unroll
            for (int j = 0; j < 4; j++) acc[i][j] = 0.f;
        for (int k = 0; k < D_; k += 4) {
            float4 a4[4], b4[4];
            #pragma unroll
            for (int i = 0; i < 4; i++) a4[i] = *(const float4*)&sQ[(ty * 4 + i) * D_ + k];
            #pragma unroll
            for (int j = 0; j < 4; j++) b4[j] = *(const float4*)&sB_[(tx * 4 + j) * D_ + k];
            #pragma unroll
            for (int i = 0; i < 4; i++)
                #pragma unroll
                for (int j = 0; j < 4; j++)
                    acc[i][j] += a4[i].x * b4[j].x + a4[i].y * b4[j].y
                               + a4[i].z * b4[j].z + a4[i].w * b4[j].w;
        }
        #pragma unroll
        for (int i = 0; i < 4; i++)
            #pragma unroll
            for (int j = 0; j < 4; j++) {
                int t = ty * 4 + i, s = tx * 4 + j;
                sA[t * TC + s] = (s <= t) ? acc[i][j] : 0.f;
            }
    }
    __syncthreads();

    float denreg = 0.f;
    if (tid < TC) {
        int t = tid;
        for (int s = 0; s < TC; s++) denreg += sA[t * TC + s];
        const float* z = g_ksum + ((size_t)(b * H_ + h) * NC + c) * D_;
        for (int k = 0; k < D_; k++) denreg += sQ[t * D_ + k] * __ldg(z + k);
    }
    for (int i = tid; i < TC * D_ / 4; i += 256) {
        int t = i >> 4, d4 = (i & 15) * 4;
        *(float4*)&sB_[t * D_ + d4] = *(const float4*)(qbase + (size_t)t * 3 * C_ + 2 * C_ + d4);
    }
    __syncthreads();

    float out[4][4];
    #pragma unroll
    for (int i = 0; i < 4; i++)
        #pragma unroll
        for (int j = 0; j < 4; j++) out[i][j] = 0.f;
    for (int s = 0; s < TC; s++) {
        float a[4];
        #pragma unroll
        for (int i = 0; i < 4; i++) a[i] = sA[(ty * 4 + i) * TC + s];
        float4 vv = *(const float4*)&sB_[s * D_ + tx * 4];
        #pragma unroll
        for (int i = 0; i < 4; i++) {
            out[i][0] += a[i] * vv.x;
            out[i][1] += a[i] * vv.y;
            out[i][2] += a[i] * vv.z;
            out[i][3] += a[i] * vv.w;
        }
    }
    __syncthreads();

    if (tid < TC) sA[tid] = denreg;
    const float* Sg = g_kv + ((size_t)((b * H_ + h) * NC + c)) * (D_ * D_);
    for (int i = tid; i < TC * D_ / 4; i += 256)
        *(float4*)&sB_[i * 4] = *(const float4*)(Sg + i * 4);
    __syncthreads();

    for (int k = 0; k < D_; k++) {
        float a[4];
        #pragma unroll
        for (int i = 0; i < 4; i++) a[i] = sQ[(ty * 4 + i) * D_ + k];
        float4 sv = *(const float4*)&sB_[k * D_ + tx * 4];
        #pragma unroll
        for (int i = 0; i < 4; i++) {
            out[i][0] += a[i] * sv.x;
            out[i][1] += a[i] * sv.y;
            out[i][2] += a[i] * sv.z;
            out[i][3] += a[i] * sv.w;
        }
    }

    // normalize + store fp16 hi/lo to y in [B,T,C] layout
    size_t ybase = ((size_t)(b * T_ + c * TC)) * C_ + h * D_;
    #pragma unroll
    for (int i = 0; i < 4; i++) {
        int t = ty * 4 + i;
        float invd = 1.0f / sA[t];
        float v[4] = { out[i][0] * invd, out[i][1] * invd,
                       out[i][2] * invd, out[i][3] * invd };
        uint32_t hi[2], lo[2];
        split4h(v, hi, lo);
        size_t off = ybase + (size_t)t * C_ + tx * 4;
        *(uint2*)(g_yh + off) = make_uint2(hi[0], hi[1]);
        *(uint2*)(g_yl + off) = make_uint2(lo[0], lo[1]);
    }
}

// ---------------- launch ----------------------------------------------------
extern "C" void kernel_launch(void* const* d_in, const int* in_sizes, int n_in,
                              void* d_out, int out_size) {
    const float* x  = (const float*)d_in[0];   // [B,T,C]
    const float* W1 = (const float*)d_in[1];   // [3C,C]
    const float* W2 = (const float*)d_in[2];   // [C,C]
    float* out = (float*)d_out;                // [B,T,C]

    __half *xnh, *xnl, *w1h, *w2h, *yh, *yl;
    float* qkv;
    cudaGetSymbolAddress((void**)&xnh, g_xnh);
    cudaGetSymbolAddress((void**)&xnl, g_xnl);
    cudaGetSymbolAddress((void**)&w1h, g_w1h);
    cudaGetSymbolAddress((void**)&w2h, g_w2h);
    cudaGetSymbolAddress((void**)&yh,  g_yh);
    cudaGetSymbolAddress((void**)&yl,  g_yl);
    cudaGetSymbolAddress((void**)&qkv, g_qkv);

    cudaFuncSetAttribute(mmagemm<true>,  cudaFuncAttributeMaxDynamicSharedMemorySize, GEMM_DSMEM);
    cudaFuncSetAttribute(mmagemm<false>, cudaFuncAttributeMaxDynamicSharedMemorySize, GEMM_DSMEM);

    // 1. layernorm -> fp16 hi/lo
    ln_kernel<<<M_, 256>>>(x);

    // weight converts (fp16 truncation)
    convert_w<<<(3 * C_ * C_ / 4 + 255) / 256, 256>>>(W1, w1h, 3 * C_ * C_ / 4);
    convert_w<<<(C_ * C_ / 4 + 255) / 256, 256>>>(W2, w2h, C_ * C_ / 4);

    // 2. qkv = xn @ W1^T (mma.sync 2-term fp16), elu+1 on q,k columns
    {
        dim3 grid(3 * C_ / 128, M_ / 128);
        mmagemm<true><<<grid, 256, GEMM_DSMEM>>>(xnh, xnl, w1h, qkv,
                                                 M_, 3 * C_, C_, 2 * C_);
    }

    // 3. linear attention (chunked, exact)
    {
        dim3 gA(NC, H_, B_);
        chunk_kv_kernel<<<gA, 256>>>();
        dim3 gP(D_ * D_ / 256, H_, B_);
        prefix_kernel<<<gP, 256>>>();
        attn_out_kernel<<<gA, 256>>>();
    }

    // 4. out = y @ W2^T (mma.sync 2-term fp16)
    {
        dim3 grid(C_ / 128, M_ / 128);
        mmagemm<false><<<grid, 256, GEMM_DSMEM>>>(yh, yl, w2h, out,
                                                  M_, C_, C_, 0);
    }
}

// round 13
// speedup vs baseline: 1.7186x; 1.3610x over previous
#include <cuda_runtime.h>
#include <cuda_fp16.h>
#include <math.h>
#include <stdint.h>

// Problem constants
#define B_  2
#define T_  2048
#define C_  1024
#define H_  16
#define D_  64
#define M_  (B_*T_)        // 4096 rows
#define TC  64             // chunk length for linear attention
#define NC  (T_/TC)        // 32 chunks

// ---------------- scratch (device globals; no cudaMalloc allowed) ----------
__device__ __half g_xnh[(size_t)M_*C_];      // normalized x, fp16
__device__ __half g_w1h[(size_t)3*C_*C_];    // W1 fp16
__device__ __half g_w2h[(size_t)C_*C_];      // W2 fp16
__device__ __half g_yh[(size_t)M_*C_];       // attention out fp16
__device__ float g_qkv[(size_t)M_*3*C_];     // qkv fp32 (elu applied q,k)
__device__ float g_kv[(size_t)B_*H_*NC*D_*D_];
__device__ float g_ksum[B_*H_*NC*D_];

// ---------------- PTX helpers -----------------------------------------------
__device__ __forceinline__ uint32_t smem_u32(const void* p) {
    uint32_t a;
    asm("{ .reg .u64 t; cvta.to.shared.u64 t, %1; cvt.u32.u64 %0, t; }"
        : "=r"(a) : "l"(p));
    return a;
}
#define CPA16(sm, gm) \
    asm volatile("cp.async.cg.shared.global [%0], [%1], 16;" :: "r"(sm), "l"(gm))
#define CPA_COMMIT() asm volatile("cp.async.commit_group;" ::: "memory")
#define CPA_WAIT1()  asm volatile("cp.async.wait_group 1;" ::: "memory")
#define CPA_WAIT0()  asm volatile("cp.async.wait_group 0;" ::: "memory")

__device__ __forceinline__ void ldsm_x4(uint32_t* r, uint32_t addr) {
    asm volatile("ldmatrix.sync.aligned.m8n8.x4.shared.b16 {%0,%1,%2,%3}, [%4];"
                 : "=r"(r[0]), "=r"(r[1]), "=r"(r[2]), "=r"(r[3]) : "r"(addr));
}
__device__ __forceinline__ void mma_f16(float* c, const uint32_t* a, const uint32_t* b) {
    asm volatile("mma.sync.aligned.m16n8k16.row.col.f32.f16.f16.f32 "
        "{%0,%1,%2,%3}, {%4,%5,%6,%7}, {%8,%9}, {%0,%1,%2,%3};"
        : "+f"(c[0]), "+f"(c[1]), "+f"(c[2]), "+f"(c[3])
        : "r"(a[0]), "r"(a[1]), "r"(a[2]), "r"(a[3]), "r"(b[0]), "r"(b[1]));
}

__device__ __forceinline__ uint32_t packh2(float a, float b) {
    __half2 t = __halves2half2(__float2half_rn(a), __float2half_rn(b));
    return *(uint32_t*)&t;
}

// ---------------- 1. LayerNorm -> fp16 ---------------------------------------
__global__ __launch_bounds__(256) void ln_kernel(const float* __restrict__ x) {
    int row = blockIdx.x;
    const float4* xr = (const float4*)(x + (size_t)row * C_);
    float4 v = xr[threadIdx.x];
    float s  = v.x + v.y + v.z + v.w;
    float sq = v.x*v.x + v.y*v.y + v.z*v.z + v.w*v.w;
    __shared__ float ss[8], ssq[8];
    #pragma unroll
    for (int o = 16; o; o >>= 1) {
        s  += __shfl_xor_sync(0xffffffffu, s,  o);
        sq += __shfl_xor_sync(0xffffffffu, sq, o);
    }
    if ((threadIdx.x & 31) == 0) { ss[threadIdx.x >> 5] = s; ssq[threadIdx.x >> 5] = sq; }
    __syncthreads();
    s = 0.f; sq = 0.f;
    #pragma unroll
    for (int i = 0; i < 8; i++) { s += ss[i]; sq += ssq[i]; }
    float mean = s * (1.0f / C_);
    float var  = sq * (1.0f / C_) - mean * mean;
    float rstd = rsqrtf(var + 1e-5f);
    uint2 o;
    o.x = packh2((v.x - mean) * rstd, (v.y - mean) * rstd);
    o.y = packh2((v.z - mean) * rstd, (v.w - mean) * rstd);
    *(uint2*)(g_xnh + (size_t)row * C_ + threadIdx.x * 4) = o;
}

// ---------------- weight convert fp32 -> fp16 (both W1, W2; one launch) -----
__global__ __launch_bounds__(256) void convert_w(
    const float* __restrict__ W1, const float* __restrict__ W2, int n1, int ntot)
{
    int i = blockIdx.x * 256 + threadIdx.x;
    if (i >= ntot) return;
    const float* src; __half* dst; int j;
    if (i < n1) { src = W1; dst = g_w1h; j = i; }
    else        { src = W2; dst = g_w2h; j = i - n1; }
    float4 v = ((const float4*)src)[j];
    uint2 o;
    o.x = packh2(v.x, v.y);
    o.y = packh2(v.z, v.w);
    ((uint2*)dst)[j] = o;
}

// ---------------- mma.sync single-term fp16 GEMM  C = A * B^T ---------------
// 128x128 CTA tile, 8 warps (warp tile 32x64), BK=32.
// 3-stage cp.async ring, ONE __syncthreads per k-chunk, XOR-swizzled smem.
// fp32 accum; inputs truncated to fp16 (error ~eps_fp16 per operand source).
// __launch_bounds__(256, 2) pins 2 CTAs/SM.
#define OFF_AH 0
#define OFF_BH 8192
#define BUF_BYTES 16384
#define GEMM_DSMEM (3*BUF_BYTES)

__device__ __forceinline__ void gstage(
    char* smbuf,
    const __half* __restrict__ Ah, const __half* __restrict__ Bh,
    int m0, int n0, int K, int k0, int tid)
{
    int row = tid >> 1;
    int c0  = tid & 1;
    uint32_t sr = smem_u32(smbuf) + row * 64;
    uint32_t sz = (row >> 1) & 3;
    const __half* pah = Ah + (size_t)(m0 + row) * K + k0;
    const __half* pbh = Bh + (size_t)(n0 + row) * K + k0;
    #pragma unroll
    for (int cc = 0; cc < 2; cc++) {
        int c = c0 + cc * 2;                 // 16B chunk 0..3
        uint32_t sw = (uint32_t)(c ^ sz) << 4;
        CPA16(sr + OFF_AH + sw, pah + c * 8);
        CPA16(sr + OFF_BH + sw, pbh + c * 8);
    }
}

template<bool ELU>
__global__ __launch_bounds__(256, 2) void mmagemm(
    const __half* __restrict__ Ah, const __half* __restrict__ Bh,
    float* __restrict__ Cm, int M, int N, int K, int elu_ncut)
{
    extern __shared__ __align__(128) char smx[];
    int tid = threadIdx.x, lane = tid & 31, wid = tid >> 5;
    int m0 = blockIdx.y * 128, n0 = blockIdx.x * 128;
    int wm = (wid & 3) * 32;            // warp m offset (2 m16 tiles)
    int wn = (wid >> 2) * 64;           // warp n offset (4 n16 tiles)

    float acc[2][8][4];
    #pragma unroll
    for (int mt = 0; mt < 2; mt++)
        #pragma unroll
        for (int nt = 0; nt < 8; nt++)
            #pragma unroll
            for (int k = 0; k < 4; k++) acc[mt][nt][k] = 0.f;

    int nk = K >> 5;                    // K/32 chunks
    gstage(smx,             Ah, Bh, m0, n0, K, 0,  tid); CPA_COMMIT();
    gstage(smx + BUF_BYTES, Ah, Bh, m0, n0, K, 32, tid); CPA_COMMIT();

    // ldmatrix lane addressing
    int a_row = lane & 15, a_c = lane >> 4;
    int b_row = (lane & 7) + (lane >> 4) * 8, b_c = (lane >> 3) & 1;
    uint32_t a_sw = (uint32_t)((a_row >> 1) & 3);
    uint32_t b_sw = (uint32_t)((b_row >> 1) & 3);

    int s_cur = 0, s_stage = 2;
    for (int kc = 0; kc < nk; kc++) {
        if (kc + 1 < nk) { CPA_WAIT1(); } else { CPA_WAIT0(); }
        __syncthreads();
        if (kc + 2 < nk) {
            gstage(smx + s_stage * BUF_BYTES, Ah, Bh,
                   m0, n0, K, (kc + 2) * 32, tid);
            CPA_COMMIT();
            if (++s_stage == 3) s_stage = 0;
        }
        uint32_t sb = smem_u32(smx) + s_cur * BUF_BYTES;
        if (++s_cur == 3) s_cur = 0;

        #pragma unroll
        for (int ks = 0; ks < 2; ks++) {
            uint32_t aH[2][4];
            uint32_t ac = (uint32_t)((ks * 2 + a_c) ^ a_sw) << 4;
            #pragma unroll
            for (int mt = 0; mt < 2; mt++) {
                uint32_t ar = sb + (wm + mt * 16 + a_row) * 64 + ac;
                ldsm_x4(aH[mt], ar + OFF_AH);
            }
            uint32_t bc = (uint32_t)((ks * 2 + b_c) ^ b_sw) << 4;
            #pragma unroll
            for (int npp = 0; npp < 2; npp++) {
                uint32_t br0 = sb + (wn + (npp*2+0) * 16 + b_row) * 64 + bc;
                uint32_t br1 = sb + (wn + (npp*2+1) * 16 + b_row) * 64 + bc;
                uint32_t bH0[4], bH1[4];
                ldsm_x4(bH0, br0 + OFF_BH);
                ldsm_x4(bH1, br1 + OFF_BH);
                // 8 MMAs over 8 distinct accumulators
                mma_f16(acc[0][npp*4+0], aH[0], bH0);
                mma_f16(acc[0][npp*4+1], aH[0], bH0 + 2);
                mma_f16(acc[1][npp*4+0], aH[1], bH0);
                mma_f16(acc[1][npp*4+1], aH[1], bH0 + 2);
                mma_f16(acc[0][npp*4+2], aH[0], bH1);
                mma_f16(acc[0][npp*4+3], aH[0], bH1 + 2);
                mma_f16(acc[1][npp*4+2], aH[1], bH1);
                mma_f16(acc[1][npp*4+3], aH[1], bH1 + 2);
            }
        }
    }

    // epilogue
    bool doelu = ELU && (n0 < elu_ncut);
    int r = lane >> 2, cp2 = (lane & 3) * 2;
    #pragma unroll
    for (int mt = 0; mt < 2; mt++) {
        #pragma unroll
        for (int nt = 0; nt < 8; nt++) {
            int mrow = m0 + wm + mt * 16 + r;
            int ncol = n0 + wn + nt * 8 + cp2;
            float v0 = acc[mt][nt][0], v1 = acc[mt][nt][1];
            float v2 = acc[mt][nt][2], v3 = acc[mt][nt][3];
            if (doelu) {
                v0 = v0 > 0.f ? v0 + 1.f : expf(v0);
                v1 = v1 > 0.f ? v1 + 1.f : expf(v1);
                v2 = v2 > 0.f ? v2 + 1.f : expf(v2);
                v3 = v3 > 0.f ? v3 + 1.f : expf(v3);
            }
            *(float2*)(Cm + (size_t)mrow * N + ncol)       = make_float2(v0, v1);
            *(float2*)(Cm + (size_t)(mrow + 8) * N + ncol) = make_float2(v2, v3);
        }
    }
}

// ---------------- 3a. per-chunk K^T V and k-sums ----------------------------
__global__ __launch_bounds__(256) void chunk_kv_kernel() {
    int c = blockIdx.x, h = blockIdx.y, b = blockIdx.z;
    __shared__ float sK[TC * D_], sV[TC * D_];
    int tid = threadIdx.x;
    const float* base = g_qkv + ((size_t)(b * T_ + c * TC)) * (3 * C_) + h * D_;
    for (int i = tid; i < TC * D_ / 4; i += 256) {
        int t = i >> 4, d4 = (i & 15) * 4;
        *(float4*)&sK[t * D_ + d4] = *(const float4*)(base + (size_t)t * 3 * C_ + C_     + d4);
        *(float4*)&sV[t * D_ + d4] = *(const float4*)(base + (size_t)t * 3 * C_ + 2 * C_ + d4);
    }
    __syncthreads();
    int tx = tid & 15, ty = tid >> 4;
    float acc[4][4];
    #pragma unroll
    for (int i = 0; i < 4; i++)
        #pragma unroll
        for (int j = 0; j < 4; j++) acc[i][j] = 0.f;
    for (int t = 0; t < TC; t++) {
        float kv[4];
        #pragma unroll
        for (int i = 0; i < 4; i++) kv[i] = sK[t * D_ + ty * 4 + i];
        float4 vv = *(const float4*)&sV[t * D_ + tx * 4];
        #pragma unroll
        for (int i = 0; i < 4; i++) {
            acc[i][0] += kv[i] * vv.x;
            acc[i][1] += kv[i] * vv.y;
            acc[i][2] += kv[i] * vv.z;
            acc[i][3] += kv[i] * vv.w;
        }
    }
    float* out = g_kv + ((size_t)((b * H_ + h) * NC + c)) * (D_ * D_);
    #pragma unroll
    for (int i = 0; i < 4; i++)
        *(float4*)(out + (ty * 4 + i) * D_ + tx * 4) =
            make_float4(acc[i][0], acc[i][1], acc[i][2], acc[i][3]);
    if (tid < D_) {
        float s = 0.f;
        for (int t = 0; t < TC; t++) s += sK[t * D_ + tid];
        g_ksum[((b * H_ + h) * NC + c) * D_ + tid] = s;
    }
}

// ---------------- 3b. exclusive prefix over chunks (parallel) ---------------
__global__ __launch_bounds__(256) void prefix_kernel() {
    int h = blockIdx.y, b = blockIdx.z;
    int e = blockIdx.x * 256 + threadIdx.x;
    size_t base = (size_t)(b * H_ + h) * NC * (D_ * D_) + e;
    float v[NC];
    #pragma unroll
    for (int c = 0; c < NC; c++) v[c] = g_kv[base + (size_t)c * (D_ * D_)];
    float acc = 0.f;
    #pragma unroll
    for (int c = 0; c < NC; c++) { float t = v[c]; v[c] = acc; acc += t; }
    #pragma unroll
    for (int c = 0; c < NC; c++) g_kv[base + (size_t)c * (D_ * D_)] = v[c];

    if (blockIdx.x == 0 && threadIdx.x < D_) {
        size_t kb = (size_t)(b * H_ + h) * NC * D_ + threadIdx.x;
        float w[NC];
        #pragma unroll
        for (int c = 0; c < NC; c++) w[c] = g_ksum[kb + c * D_];
        float a = 0.f;
        #pragma unroll
        for (int c = 0; c < NC; c++) { float t = w[c]; w[c] = a; a += t; }
        #pragma unroll
        for (int c = 0; c < NC; c++) g_ksum[kb + c * D_] = w[c];
    }
}

// ---------------- 3c. per-chunk output -> y fp16 ----------------------------
__global__ __launch_bounds__(256) void attn_out_kernel() {
    int c = blockIdx.x, h = blockIdx.y, b = blockIdx.z;
    __shared__ float sQ[TC * D_];
    __shared__ float sB_[TC * D_];
    __shared__ float sA[TC * TC];
    int tid = threadIdx.x, tx = tid & 15, ty = tid >> 4;
    const float* qbase = g_qkv + ((size_t)(b * T_ + c * TC)) * (3 * C_) + h * D_;

    for (int i = tid; i < TC * D_ / 4; i += 256) {
        int t = i >> 4, d4 = (i & 15) * 4;
        *(float4*)&sQ[t * D_ + d4]  = *(const float4*)(qbase + (size_t)t * 3 * C_ + d4);
        *(float4*)&sB_[t * D_ + d4] = *(const float4*)(qbase + (size_t)t * 3 * C_ + C_ + d4);
    }
    __syncthreads();

    {
        float acc[4][4];
        #pragma unroll
        for (int i = 0; i < 4; i++)
            #pragma unroll
            for (int j = 0; j < 4; j++) acc[i][j] = 0.f;
        for (int k = 0; k < D_; k += 4) {
            float4 a4[4], b4[4];
            #pragma unroll
            for (int i = 0; i < 4; i++) a4[i] = *(const float4*)&sQ[(ty * 4 + i) * D_ + k];
            #pragma unroll
            for (int j = 0; j < 4; j++) b4[j] = *(const float4*)&sB_[(tx * 4 + j) * D_ + k];
            #pragma unroll
            for (int i = 0; i < 4; i++)
                #pragma unroll
                for (int j = 0; j < 4; j++)
                    acc[i][j] += a4[i].x * b4[j].x + a4[i].y * b4[j].y
                               + a4[i].z * b4[j].z + a4[i].w * b4[j].w;
        }
        #pragma unroll
        for (int i = 0; i < 4; i++)
            #pragma unroll
            for (int j = 0; j < 4; j++) {
                int t = ty * 4 + i, s = tx * 4 + j;
                sA[t * TC + s] = (s <= t) ? acc[i][j] : 0.f;
            }
    }
    __syncthreads();

    float denreg = 0.f;
    if (tid < TC) {
        int t = tid;
        for (int s = 0; s < TC; s++) denreg += sA[t * TC + s];
        const float* z = g_ksum + ((size_t)(b * H_ + h) * NC + c) * D_;
        for (int k = 0; k < D_; k++) denreg += sQ[t * D_ + k] * __ldg(z + k);
    }
    for (int i = tid; i < TC * D_ / 4; i += 256) {
        int t = i >> 4, d4 = (i & 15) * 4;
        *(float4*)&sB_[t * D_ + d4] = *(const float4*)(qbase + (size_t)t * 3 * C_ + 2 * C_ + d4);
    }
    __syncthreads();

    float out[4][4];
    #pragma unroll
    for (int i = 0; i < 4; i++)
        #pragma unroll
        for (int j = 0; j < 4; j++) out[i][j] = 0.f;
    for (int s = 0; s < TC; s++) {
        float a[4];
        #pragma unroll
        for (int i = 0; i < 4; i++) a[i] = sA[(ty * 4 + i) * TC + s];
        float4 vv = *(const float4*)&sB_[s * D_ + tx * 4];
        #pragma unroll
        for (int i = 0; i < 4; i++) {
            out[i][0] += a[i] * vv.x;
            out[i][1] += a[i] * vv.y;
            out[i][2] += a[i] * vv.z;
            out[i][3] += a[i] * vv.w;
        }
    }
    __syncthreads();

    if (tid < TC) sA[tid] = denreg;
    const float* Sg = g_kv + ((size_t)((b * H_ + h) * NC + c)) * (D_ * D_);
    for (int i = tid; i < TC * D_ / 4; i += 256)
        *(float4*)&sB_[i * 4] = *(const float4*)(Sg + i * 4);
    __syncthreads();

    for (int k = 0; k < D_; k++) {
        float a[4];
        #pragma unroll
        for (int i = 0; i < 4; i++) a[i] = sQ[(ty * 4 + i) * D_ + k];
        float4 sv = *(const float4*)&sB_[k * D_ + tx * 4];
        #pragma unroll
        for (int i = 0; i < 4; i++) {
            out[i][0] += a[i] * sv.x;
            out[i][1] += a[i] * sv.y;
            out[i][2] += a[i] * sv.z;
            out[i][3] += a[i] * sv.w;
        }
    }

    // normalize + store fp16 to y in [B,T,C] layout
    size_t ybase = ((size_t)(b * T_ + c * TC)) * C_ + h * D_;
    #pragma unroll
    for (int i = 0; i < 4; i++) {
        int t = ty * 4 + i;
        float invd = 1.0f / sA[t];
        uint2 o;
        o.x = packh2(out[i][0] * invd, out[i][1] * invd);
        o.y = packh2(out[i][2] * invd, out[i][3] * invd);
        *(uint2*)(g_yh + ybase + (size_t)t * C_ + tx * 4) = o;
    }
}

// ---------------- launch ----------------------------------------------------
extern "C" void kernel_launch(void* const* d_in, const int* in_sizes, int n_in,
                              void* d_out, int out_size) {
    const float* x  = (const float*)d_in[0];   // [B,T,C]
    const float* W1 = (const float*)d_in[1];   // [3C,C]
    const float* W2 = (const float*)d_in[2];   // [C,C]
    float* out = (float*)d_out;                // [B,T,C]

    __half *xnh, *w1h, *w2h, *yh;
    float* qkv;
    cudaGetSymbolAddress((void**)&xnh, g_xnh);
    cudaGetSymbolAddress((void**)&w1h, g_w1h);
    cudaGetSymbolAddress((void**)&w2h, g_w2h);
    cudaGetSymbolAddress((void**)&yh,  g_yh);
    cudaGetSymbolAddress((void**)&qkv, g_qkv);

    cudaFuncSetAttribute(mmagemm<true>,  cudaFuncAttributeMaxDynamicSharedMemorySize, GEMM_DSMEM);
    cudaFuncSetAttribute(mmagemm<false>, cudaFuncAttributeMaxDynamicSharedMemorySize, GEMM_DSMEM);

    // 1. layernorm -> fp16
    ln_kernel<<<M_, 256>>>(x);

    // weight converts (single launch for W1 + W2)
    {
        int n1 = 3 * C_ * C_ / 4, ntot = n1 + C_ * C_ / 4;
        convert_w<<<(ntot + 255) / 256, 256>>>(W1, W2, n1, ntot);
    }

    // 2. qkv = xn @ W1^T (mma.sync single-term fp16), elu+1 on q,k columns
    {
        dim3 grid(3 * C_ / 128, M_ / 128);
        mmagemm<true><<<grid, 256, GEMM_DSMEM>>>(xnh, w1h, qkv,
                                                 M_, 3 * C_, C_, 2 * C_);
    }

    // 3. linear attention (chunked, exact fp32)
    {
        dim3 gA(NC, H_, B_);
        chunk_kv_kernel<<<gA, 256>>>();
        dim3 gP(D_ * D_ / 256, H_, B_);
        prefix_kernel<<<gP, 256>>>();
        attn_out_kernel<<<gA, 256>>>();
    }

    // 4. out = y @ W2^T (mma.sync single-term fp16)
    {
        dim3 grid(C_ / 128, M_ / 128);
        mmagemm<false><<<grid, 256, GEMM_DSMEM>>>(yh, w2h, out,
                                                  M_, C_, C_, 0);
    }
}